// round 2
// baseline (speedup 1.0000x reference)
#include <cuda_runtime.h>

#define NN 64
#define TT 5
#define VV 64
#define FF 256
#define TMID 2   // T//2

// Each block handles one (n, half): 32 full rows i of the 64x64 similarity
// matrix for graph n. Rows are complete (all 64 j), so the column-sum
// denominator (== row sum by exact symmetry of S) is computed locally.
__global__ __launch_bounds__(256, 1)
void gl_kernel(const float* __restrict__ x,
               const float* __restrict__ a,
               float* __restrict__ out) {
    extern __shared__ float sm[];
    float* xsT = sm;             // [FF][VV]  transposed slice, 64 KB
    float* a_s = sm + FF * VV;   // [FF]

    const int b    = blockIdx.x;
    const int n    = b >> 1;
    const int half = b & 1;
    const int tid  = threadIdx.x;

    const float* xm = x + ((size_t)n * TT + TMID) * (size_t)(VV * FF);

    // ---- Stage xm[n] transposed into smem: xsT[f*VV + v] = xm[v*FF + f] ----
    // Coalesced float4 reads along f; strided smem writes (conflict-free:
    // f*64 is a multiple of 32 banks, v varies across threads).
    const float4* x4 = (const float4*)xm;
    #pragma unroll
    for (int idx = tid; idx < VV * (FF / 4); idx += 256) {
        int v  = idx >> 6;       // FF/4 == 64
        int f4 = idx & 63;
        float4 val = x4[v * (FF / 4) + f4];
        int f = f4 * 4;
        xsT[(f + 0) * VV + v] = val.x;
        xsT[(f + 1) * VV + v] = val.y;
        xsT[(f + 2) * VV + v] = val.z;
        xsT[(f + 3) * VV + v] = val.w;
    }
    if (tid < FF) a_s[tid] = a[tid];
    __syncthreads();

    const int warp   = tid >> 5;
    const int lane   = tid & 31;
    const int i_base = half * 32 + warp * 4;  // 8 warps x 4 rows = 32 rows
    const int j0     = lane * 2;              // 2 j's per lane (float2)

    float acc[4][2];
    #pragma unroll
    for (int ii = 0; ii < 4; ii++) { acc[ii][0] = 0.f; acc[ii][1] = 0.f; }

    // ---- Main accumulation over f ----
    #pragma unroll 4
    for (int f = 0; f < FF; f++) {
        const float* row = &xsT[f * VV];
        float2 xj = *(const float2*)&row[j0];   // conflict-free LDS.64
        float av  = a_s[f];                      // broadcast
        float xi0 = row[i_base + 0];             // broadcasts
        float xi1 = row[i_base + 1];
        float xi2 = row[i_base + 2];
        float xi3 = row[i_base + 3];

        acc[0][0] += av * fabsf(xi0 - xj.x);
        acc[0][1] += av * fabsf(xi0 - xj.y);
        acc[1][0] += av * fabsf(xi1 - xj.x);
        acc[1][1] += av * fabsf(xi1 - xj.y);
        acc[2][0] += av * fabsf(xi2 - xj.x);
        acc[2][1] += av * fabsf(xi2 - xj.y);
        acc[3][0] += av * fabsf(xi3 - xj.x);
        acc[3][1] += av * fabsf(xi3 - xj.y);
    }

    // ---- exp, row-sum (== reference column-sum by symmetry), normalize ----
    const float LOG2E = 1.4426950408889634f;
    #pragma unroll
    for (int ii = 0; ii < 4; ii++) {
        float s0 = exp2f(acc[ii][0] * LOG2E);
        float s1 = exp2f(acc[ii][1] * LOG2E);

        float r = s0 + s1;
        #pragma unroll
        for (int off = 16; off > 0; off >>= 1)
            r += __shfl_xor_sync(0xFFFFFFFFu, r, off);
        float inv = 1.0f / r;

        int i = i_base + ii;
        float2 o;
        o.x = s0 * inv;
        o.y = s1 * inv;
        *(float2*)&out[((size_t)(n * VV + i)) * VV + j0] = o;
    }
}

extern "C" void kernel_launch(void* const* d_in, const int* in_sizes, int n_in,
                              void* d_out, int out_size) {
    const float* x = (const float*)d_in[0];   // (64,5,64,256) float32
    const float* a = (const float*)d_in[1];   // (256,1) float32
    float* out = (float*)d_out;               // (64,64,64) float32

    const int smem_bytes = (FF * VV + FF) * (int)sizeof(float);  // ~66.5 KB
    cudaFuncSetAttribute(gl_kernel, cudaFuncAttributeMaxDynamicSharedMemorySize,
                         smem_bytes);
    gl_kernel<<<NN * 2, 256, smem_bytes>>>(x, a, out);
}